// round 13
// baseline (speedup 1.0000x reference)
#include <cuda_runtime.h>
#include <cuda_fp16.h>

// GCN 2-layer regression on GB300. N=100000 nodes, E=3.2M edges, d_in=128, h=16.
//
// Bucketed-CSR, oct-per-node gather over fp16 feature rows (32B/row),
// warp-specialized fill||gemm overlap. Accumulation is fp32 throughout;
// only the two intermediate feature tables are stored as fp16.
//   kernel A: warps 0-5 fill CSR buckets; warps 6-7 raw xw = x @ W1 (fp32)
//   kernel B: dis = rsqrt(cnt+1); pack g_xwh = fp16(dis * xw)
//   kernel C: h1 = dis*(self+sum nbr) -> relu+b1 -> @W2 -> *dis -> fp16 g_xw2h
//   kernel D: h2 likewise -> relu+b2 -> .Wl+bl -> out  (+ cnt self-reset)
// g_cnt is zeroed in D's epilogue (device globals start zeroed; every run
// leaves them zeroed), so no separate zero pass is needed.

#define MAXN 100000
#define CAP  128            // per-node bucket capacity (Poisson(32) max deg ~65)

__device__ float g_xwf [MAXN * 16];    // raw fp32 x@W1 (scratch)
__device__ uint4 g_xwh [MAXN * 2];     // layer-1 dis-scaled features, fp16 x16
__device__ uint4 g_xw2h[MAXN * 2];     // layer-2 dis-scaled features, fp16 x16
__device__ float g_dis [MAXN];         // deg^{-1/2}
__device__ int   g_cnt [MAXN];         // indegree / fill cursors (self-reset)
__device__ int   g_csr [MAXN * CAP];   // bucketed src ids

#define FILL_WARPS 6
#define FILL_THR   (FILL_WARPS * 32)   // 192 fill threads per CTA

// ---------------------------------------------------------------------------
// Kernel A: fused fill (warps 0-5) + raw GEMM1 (warps 6-7).  (R10 structure.)
__global__ void __launch_bounds__(256)
fillgemm_kernel(const float* __restrict__ x, const float* __restrict__ W1,
                const void* __restrict__ ei, long long E, int N) {
    __shared__ float ws[128 * 16];   // W1
    __shared__ float xs[8 * 132];    // x tile for gemm warps (padded)
    __shared__ int   s_is64;

    const int tid = threadIdx.x;
    const int wid = tid >> 5;

    if (tid == 0) {
        // dtype detect: int64 ids < 2^31 -> every odd 32-bit word is 0.
        const int* w = (const int*)ei;
        int az = 1;
        for (int k = 0; k < 64; k++)
            if (w[2 * k + 1] != 0) { az = 0; break; }
        s_is64 = az;
    }
    for (int i = tid; i < 128 * 16; i += 256) ws[i] = W1[i];
    __syncthreads();

    if (wid < FILL_WARPS) {
        // ------------------- fill: 8 edges per thread ---------------------
        const int is64 = s_is64;
        const long long F = (long long)gridDim.x * FILL_THR;
        for (long long c = (long long)blockIdx.x * FILL_THR + tid;
             c * 8 < E; c += F) {
            const long long e0 = c * 8;
            int s[8], d[8];
            int n;
            if (e0 + 8 <= E && (E & 1) == 0) {
                n = 8;
                if (is64) {
                    const longlong2* sp = (const longlong2*)ei;
                    const longlong2* dp = (const longlong2*)((const long long*)ei + E);
#pragma unroll
                    for (int k = 0; k < 4; k++) {
                        longlong2 a = sp[c * 4 + k];
                        s[2 * k] = (int)a.x; s[2 * k + 1] = (int)a.y;
                    }
#pragma unroll
                    for (int k = 0; k < 4; k++) {
                        longlong2 a = dp[c * 4 + k];
                        d[2 * k] = (int)a.x; d[2 * k + 1] = (int)a.y;
                    }
                } else if ((E & 3) == 0) {
                    const int4* sp = (const int4*)ei;
                    const int4* dp = (const int4*)((const int*)ei + E);
#pragma unroll
                    for (int k = 0; k < 2; k++) {
                        int4 a = sp[c * 2 + k];
                        s[4 * k] = a.x; s[4 * k + 1] = a.y;
                        s[4 * k + 2] = a.z; s[4 * k + 3] = a.w;
                    }
#pragma unroll
                    for (int k = 0; k < 2; k++) {
                        int4 a = dp[c * 2 + k];
                        d[4 * k] = a.x; d[4 * k + 1] = a.y;
                        d[4 * k + 2] = a.z; d[4 * k + 3] = a.w;
                    }
                } else {
                    const int* w = (const int*)ei;
#pragma unroll
                    for (int k = 0; k < 8; k++) { s[k] = w[e0 + k]; d[k] = w[E + e0 + k]; }
                }
            } else {
                n = (int)(E - e0 < 8 ? E - e0 : 8);
                for (int k = 0; k < n; k++) {
                    if (is64) {
                        s[k] = (int)((const long long*)ei)[e0 + k];
                        d[k] = (int)((const long long*)ei)[E + e0 + k];
                    } else {
                        s[k] = ((const int*)ei)[e0 + k];
                        d[k] = ((const int*)ei)[E + e0 + k];
                    }
                }
            }
            int pos[8];
#pragma unroll
            for (int k = 0; k < 8; k++)
                if (k < n) pos[k] = atomicAdd(&g_cnt[d[k]], 1);
#pragma unroll
            for (int k = 0; k < 8; k++)
                if (k < n) g_csr[((size_t)d[k] << 7) + pos[k]] = s[k];
        }
    } else {
        // ------------------- gemm: raw xw = x @ W1 (fp32) -----------------
        const int gtid = tid - FILL_THR;     // 0..63
        for (int tile = blockIdx.x; tile * 8 < N; tile += gridDim.x) {
            const int base = tile * 8;
            const int rows = min(8, N - base);
            const float4* xg = (const float4*)(x + (size_t)base * 128);
            for (int i = gtid; i < rows * 32; i += 64) {
                float4 v = xg[i];
                int r = i >> 5, cc = (i & 31) * 4;
                float* p = xs + r * 132 + cc;
                p[0] = v.x; p[1] = v.y; p[2] = v.z; p[3] = v.w;
            }
            asm volatile("bar.sync 1, 64;" ::: "memory");

            const int node = gtid >> 3;     // 0..7
            const int j0   = gtid & 7;      // cols j0 and j0+8
            if (node < rows) {
                const float* xr = xs + node * 132;
                float a0 = 0.f, a1 = 0.f;
#pragma unroll
                for (int k = 0; k < 128; k++) {
                    float xv = xr[k];
                    a0 = fmaf(xv, ws[k * 16 + j0],     a0);
                    a1 = fmaf(xv, ws[k * 16 + j0 + 8], a1);
                }
                float* xwp = g_xwf + (size_t)(base + node) * 16;
                xwp[j0]     = a0;           // raw (scaled+packed by scale_kernel)
                xwp[j0 + 8] = a1;
            }
            asm volatile("bar.sync 1, 64;" ::: "memory");
        }
    }
}

// ---------------------------------------------------------------------------
// fp16 helpers
__device__ __forceinline__ uint4 pack8(const float* v) {
    __half2 p0 = __floats2half2_rn(v[0], v[1]);
    __half2 p1 = __floats2half2_rn(v[2], v[3]);
    __half2 p2 = __floats2half2_rn(v[4], v[5]);
    __half2 p3 = __floats2half2_rn(v[6], v[7]);
    uint4 o;
    o.x = *(unsigned*)&p0; o.y = *(unsigned*)&p1;
    o.z = *(unsigned*)&p2; o.w = *(unsigned*)&p3;
    return o;
}

__device__ __forceinline__ void acc8(float* a, uint4 hv) {
    const __half2* hp = (const __half2*)&hv;
#pragma unroll
    for (int i = 0; i < 4; i++) {
        float2 f = __half22float2(hp[i]);
        a[2 * i]     += f.x;
        a[2 * i + 1] += f.y;
    }
}

// ---------------------------------------------------------------------------
// Kernel B: dis = rsqrt(cnt+1); g_xwh = fp16(dis * g_xwf). One uint4/thread.
__global__ void scale_kernel(int N) {
    int i = blockIdx.x * blockDim.x + threadIdx.x;
    if (i >= N * 2) return;
    int node = i >> 1;
    int jh   = i & 1;
    float dv = rsqrtf((float)(g_cnt[node] + 1));
    const float* src = g_xwf + (size_t)node * 16 + jh * 8;
    float v[8];
#pragma unroll
    for (int k = 0; k < 8; k++) v[k] = src[k] * dv;
    g_xwh[i] = pack8(v);
    if (jh == 0) g_dis[node] = dv;
}

// ---------------------------------------------------------------------------
// Oct-cooperative fp16 neighbor sum. 8 threads per node:
//   jh = lane&1 (which 8-col half-row), chunk c = (lane>>1)&3.
// Chunk c handles neighbors [4c..4c+3] + 16-stride; the jh-pair touches one
// 32B sector per neighbor row. Folds chunks via shfl_xor strides 2,4.
// Leaves a[0..7] = dis * (self + sum) for cols jh*8..jh*8+7 (all lanes).
__device__ __forceinline__ void gather_h(const uint4* __restrict__ feat,
                                         int node, int lane, int cnt, float* a) {
    const int jh = lane & 1;
    const int c  = (lane >> 1) & 3;
    const int beg = node << 7;

#pragma unroll
    for (int i = 0; i < 8; i++) a[i] = 0.f;

    for (int k = 4 * c; k < cnt; k += 16) {
        // k is 4-aligned and < cnt <= 128: int4 stays inside the bucket.
        int4 s4 = *(const int4*)&g_csr[beg + k];
        if (k + 0 < cnt) acc8(a, __ldg(feat + ((size_t)s4.x * 2 + jh)));
        if (k + 1 < cnt) acc8(a, __ldg(feat + ((size_t)s4.y * 2 + jh)));
        if (k + 2 < cnt) acc8(a, __ldg(feat + ((size_t)s4.z * 2 + jh)));
        if (k + 3 < cnt) acc8(a, __ldg(feat + ((size_t)s4.w * 2 + jh)));
    }

    if (c == 0)                      // self loop, once per half-row
        acc8(a, __ldg(feat + ((size_t)node * 2 + jh)));

    // fold the 4 chunks (lane bits 1,2)
#pragma unroll
    for (int o = 2; o <= 4; o <<= 1)
#pragma unroll
        for (int i = 0; i < 8; i++)
            a[i] += __shfl_xor_sync(0xFFFFFFFFu, a[i], o);

    float dd = g_dis[node];
#pragma unroll
    for (int i = 0; i < 8; i++) a[i] *= dd;
}

// Kernel C: h1 = gather(g_xwh); t = relu(h1+b1); g_xw2h = fp16(dis * (t @ W2))
__global__ void gather1_kernel(const float* __restrict__ W2,
                               const float* __restrict__ b1, int N) {
    __shared__ float ws[16 * 16];
    __shared__ float bs[16];
    const int tid = threadIdx.x;
    ws[tid] = W2[tid & 255];         // 256 threads load all of W2
    if (tid < 16) bs[tid] = b1[tid];
    __syncthreads();

    const int lane = tid & 31;
    int node = blockIdx.x * (blockDim.x >> 3) + (tid >> 3);
    bool valid = node < N;
    if (!valid) node = 0;
    const int jh = lane & 1;

    float a[8];
    gather_h(g_xwh, node, lane, g_cnt[node], a);

    // relu + bias on my half-row
    float t[8];
#pragma unroll
    for (int i = 0; i < 8; i++)
        t[i] = fmaxf(a[i] + bs[jh * 8 + i], 0.f);

    // exchange halves with the jh-partner (lane ^ 1)
    float tf[16];
#pragma unroll
    for (int i = 0; i < 8; i++) {
        tf[jh * 8 + i]       = t[i];
        tf[(jh ^ 1) * 8 + i] = __shfl_xor_sync(0xFFFFFFFFu, t[i], 1);
    }

    // my 8 output cols: acc[cc] = sum_k tf[k] * W2[k][jh*8+cc]
    float acc[8];
#pragma unroll
    for (int i = 0; i < 8; i++) acc[i] = 0.f;
#pragma unroll
    for (int k = 0; k < 16; k++) {
        float tk = tf[k];
#pragma unroll
        for (int cc = 0; cc < 8; cc++)
            acc[cc] = fmaf(tk, ws[k * 16 + jh * 8 + cc], acc[cc]);
    }

    if (valid && (lane & 6) == 0) {  // chunk 0 lanes (jh=0,1) write the row
        float dv = g_dis[node];
#pragma unroll
        for (int i = 0; i < 8; i++) acc[i] *= dv;
        g_xw2h[(size_t)node * 2 + jh] = pack8(acc);
    }
}

// Kernel D: h2 = gather(g_xw2h); out = relu(h2+b2) . Wl + bl; reset g_cnt.
__global__ void gather2_kernel(const float* __restrict__ b2,
                               const float* __restrict__ Wl,
                               const float* __restrict__ bl,
                               float* __restrict__ out, int N) {
    __shared__ float bs[16];
    __shared__ float wl[16];
    __shared__ float bl0;
    const int tid = threadIdx.x;
    if (tid < 16) { bs[tid] = b2[tid]; wl[tid] = Wl[tid]; }
    if (tid == 0) bl0 = bl[0];
    __syncthreads();

    const int lane = tid & 31;
    int node = blockIdx.x * (blockDim.x >> 3) + (tid >> 3);
    bool valid = node < N;
    if (!valid) node = 0;
    const int jh = lane & 1;

    int cnt = g_cnt[node];
    float a[8];
    gather_h(g_xw2h, node, lane, cnt, a);

    float s = 0.f;
#pragma unroll
    for (int i = 0; i < 8; i++)
        s = fmaf(fmaxf(a[i] + bs[jh * 8 + i], 0.f), wl[jh * 8 + i], s);

    s += __shfl_xor_sync(0xFFFFFFFFu, s, 1);   // combine the two half-rows

    if (valid && (lane & 7) == 0) {
        out[node] = s + bl0;
        g_cnt[node] = 0;             // reset for next launch (after last read)
    }
}

// ---------------------------------------------------------------------------
extern "C" void kernel_launch(void* const* d_in, const int* in_sizes, int n_in,
                              void* d_out, int out_size) {
    const float* x  = (const float*)d_in[0];
    const void*  ei = d_in[1];
    const float* W1 = (const float*)d_in[2];
    const float* b1 = (const float*)d_in[3];
    const float* W2 = (const float*)d_in[4];
    const float* b2 = (const float*)d_in[5];
    const float* Wl = (const float*)d_in[6];
    const float* bl = (const float*)d_in[7];
    float* out = (float*)d_out;

    const int       N = in_sizes[0] / 128;
    const long long E = (long long)in_sizes[1] / 2;

    const int fgBlocks     = (int)(((E + 7) / 8 + FILL_THR - 1) / FILL_THR);
    const int scaleBlocks  = (N * 2 + 255) / 256;
    const int octsPerBlk   = 32;                      // 256 threads
    const int gatherBlocks = (N + octsPerBlk - 1) / octsPerBlk;

    fillgemm_kernel<<<fgBlocks, 256>>>(x, W1, ei, E, N);        // CSR + raw xw
    scale_kernel<<<scaleBlocks, 256>>>(N);                      // dis + fp16 pack
    gather1_kernel<<<gatherBlocks, 256>>>(W2, b1, N);           // g_xw2h
    gather2_kernel<<<gatherBlocks, 256>>>(b2, Wl, bl, out, N);  // out (+ cnt reset)
}